// round 2
// baseline (speedup 1.0000x reference)
#include <cuda_runtime.h>
#include <math.h>

#define NN 50000
#define EE 800000
#define D 96
#define HID 32
#define HEADS 3
#define FIN 16
#define F0 8
#define EDIM 4

// ---- scratch (static device globals; no allocations allowed) ----
__device__ float g_h0[NN * F0];
__device__ float g_h1[NN * D];
__device__ float g_Q[NN * D];
__device__ float g_K[NN * D];
__device__ float g_V[NN * D];
__device__ float g_S[NN * D];
__device__ int   g_cnt[NN];
__device__ int   g_rowptr[NN + 1];
__device__ int   g_cur[NN];
__device__ int   g_psrc[EE];     // src index in CSR-permuted order
__device__ float4 g_pea[EE];     // edge_attr in CSR-permuted order

// ---------------- layer 0: h0 = tanh(x @ W1 + b1), 16 -> 8 ----------------
__global__ void k_l0(const float* __restrict__ x, const float* __restrict__ W1,
                     const float* __restrict__ b1, int n) {
    int i = blockIdx.x * blockDim.x + threadIdx.x;
    if (i >= n) return;
    float xr[FIN];
    const float4* xv = reinterpret_cast<const float4*>(x + i * FIN);
#pragma unroll
    for (int j = 0; j < 4; j++) {
        float4 t = xv[j];
        xr[j * 4 + 0] = t.x; xr[j * 4 + 1] = t.y; xr[j * 4 + 2] = t.z; xr[j * 4 + 3] = t.w;
    }
#pragma unroll
    for (int o = 0; o < F0; o++) {
        float acc = b1[o];
#pragma unroll
        for (int k = 0; k < FIN; k++) acc += xr[k] * W1[k * F0 + o];
        g_h0[i * F0 + o] = tanhf(acc);
    }
}

// ---------------- CSR build ----------------
__global__ void k_zero(int n) {
    int i = blockIdx.x * blockDim.x + threadIdx.x;
    if (i < n) g_cnt[i] = 0;
}

__global__ void k_hist(const int* __restrict__ dst, int e) {
    int i = blockIdx.x * blockDim.x + threadIdx.x;
    if (i < e) atomicAdd(&g_cnt[dst[i]], 1);
}

__global__ void k_scan(int n, int etot) {
    __shared__ int sh[1024];
    int t = threadIdx.x;
    int chunk = (n + 1023) >> 10;
    int beg = t * chunk;
    int end = min(beg + chunk, n);
    int sum = 0;
    for (int i = beg; i < end; i++) sum += g_cnt[i];
    sh[t] = sum;
    __syncthreads();
    for (int off = 1; off < 1024; off <<= 1) {
        int v = (t >= off) ? sh[t - off] : 0;
        __syncthreads();
        sh[t] += v;
        __syncthreads();
    }
    int run = sh[t] - sum;  // exclusive prefix
    for (int i = beg; i < end; i++) {
        g_rowptr[i] = run;
        g_cur[i] = run;
        run += g_cnt[i];
    }
    if (t == 1023) g_rowptr[n] = etot;
}

// scatter: also permute src and edge_attr into CSR order so the attention
// loop streams them sequentially (K/V remain the only random gathers).
__global__ void k_scatter(const int* __restrict__ src, const int* __restrict__ dst,
                          const float4* __restrict__ ea, int e) {
    int i = blockIdx.x * blockDim.x + threadIdx.x;
    if (i >= e) return;
    int d = dst[i];
    int pos = atomicAdd(&g_cur[d], 1);
    g_psrc[pos] = src[i];
    g_pea[pos] = ea[i];
}

// ---------------- fused projection: Q,K,V,S = in @ {Wq,Wk,Wv,Ws} + bias ----------------
// layer_in: 0 -> read g_h0 (FI=8), 1 -> read g_h1 (FI=96)
template <int FI, int NB>
__global__ void k_proj(int layer_in,
                       const float* __restrict__ Wq, const float* __restrict__ bq,
                       const float* __restrict__ Wk, const float* __restrict__ bk,
                       const float* __restrict__ Wv, const float* __restrict__ bv,
                       const float* __restrict__ Ws, const float* __restrict__ bs,
                       int n) {
    const float* in = (layer_in == 0) ? g_h0 : g_h1;
    __shared__ float sh[NB][FI];
    int node0 = blockIdx.x * NB;
    int d = threadIdx.x;  // 0..95
    for (int idx = d; idx < NB * FI; idx += D) {
        int j = idx / FI, k = idx % FI;
        int nd = node0 + j;
        sh[j][k] = (nd < n) ? in[nd * FI + k] : 0.0f;
    }
    __syncthreads();
    float aq[NB], ak[NB], av[NB], as_[NB];
    float vbq = bq[d], vbk = bk[d], vbv = bv[d], vbs = bs[d];
#pragma unroll
    for (int j = 0; j < NB; j++) { aq[j] = vbq; ak[j] = vbk; av[j] = vbv; as_[j] = vbs; }
    for (int k = 0; k < FI; k++) {
        float wq = Wq[k * D + d], wk = Wk[k * D + d], wv = Wv[k * D + d], ws = Ws[k * D + d];
#pragma unroll
        for (int j = 0; j < NB; j++) {
            float h = sh[j][k];
            aq[j] += h * wq; ak[j] += h * wk; av[j] += h * wv; as_[j] += h * ws;
        }
    }
#pragma unroll
    for (int j = 0; j < NB; j++) {
        int nd = node0 + j;
        if (nd < n) {
            g_Q[nd * D + d] = aq[j];
            g_K[nd * D + d] = ak[j];
            g_V[nd * D + d] = av[j];
            g_S[nd * D + d] = as_[j];
        }
    }
}

// ---------------- attention: warp per destination node, online softmax ----------------
// out_sel: 0 -> write g_h1 (layer 1), 1 -> write `out` param (layer 2)
__global__ void k_attn(const float* __restrict__ We, int out_sel,
                       float* __restrict__ out, int n) {
    int w = (blockIdx.x * blockDim.x + threadIdx.x) >> 5;
    int lane = threadIdx.x & 31;
    if (w >= n) return;
    float* optr = (out_sel == 0) ? g_h1 : out;

    // We columns this lane needs: [EDIM][HEADS]
    float we[EDIM][HEADS];
#pragma unroll
    for (int j = 0; j < EDIM; j++)
#pragma unroll
        for (int c = 0; c < HEADS; c++) we[j][c] = We[j * D + c * HID + lane];

    float q[HEADS];
#pragma unroll
    for (int c = 0; c < HEADS; c++) q[c] = g_Q[w * D + c * HID + lane];

    float m[HEADS], s[HEADS], acc[HEADS];
#pragma unroll
    for (int c = 0; c < HEADS; c++) { m[c] = -1e30f; s[c] = 0.0f; acc[c] = 0.0f; }

    int beg = g_rowptr[w];
    int end = g_rowptr[w + 1];
    const float sc = 0.17677669529663687f;  // 1/sqrt(32)

    for (int i = beg; i < end; i++) {
        int sidx = g_psrc[i];          // sequential
        float4 ea = g_pea[i];          // sequential 16B
        float eev[HEADS];
#pragma unroll
        for (int c = 0; c < HEADS; c++)
            eev[c] = ea.x * we[0][c] + ea.y * we[1][c] + ea.z * we[2][c] + ea.w * we[3][c];
        int kb = sidx * D;
        // K and V loads are independent -> overlap L2 latency
        float k0 = g_K[kb + lane];
        float k1 = g_K[kb + HID + lane];
        float k2 = g_K[kb + 2 * HID + lane];
        float v0 = g_V[kb + lane];
        float v1 = g_V[kb + HID + lane];
        float v2 = g_V[kb + 2 * HID + lane];
        float p0 = q[0] * (k0 + eev[0]);
        float p1 = q[1] * (k1 + eev[1]);
        float p2 = q[2] * (k2 + eev[2]);
#pragma unroll
        for (int off = 16; off > 0; off >>= 1) {
            p0 += __shfl_xor_sync(0xFFFFFFFFu, p0, off);
            p1 += __shfl_xor_sync(0xFFFFFFFFu, p1, off);
            p2 += __shfl_xor_sync(0xFFFFFFFFu, p2, off);
        }
        float l[HEADS] = {p0 * sc, p1 * sc, p2 * sc};
        float vv[HEADS] = {v0 + eev[0], v1 + eev[1], v2 + eev[2]};
#pragma unroll
        for (int c = 0; c < HEADS; c++) {
            float nm = fmaxf(m[c], l[c]);
            float corr = __expf(m[c] - nm);
            float p = __expf(l[c] - nm);
            s[c] = s[c] * corr + p;
            m[c] = nm;
            acc[c] = acc[c] * corr + p * vv[c];
        }
    }
#pragma unroll
    for (int c = 0; c < HEADS; c++) {
        float o = acc[c] / (s[c] + 1e-16f) + g_S[w * D + c * HID + lane];
        optr[w * D + c * HID + lane] = tanhf(o);
    }
}

// ---------------- launch ----------------
extern "C" void kernel_launch(void* const* d_in, const int* in_sizes, int n_in,
                              void* d_out, int out_size) {
    const float* x     = (const float*)d_in[0];
    const int*   eidx  = (const int*)d_in[1];
    const float* eattr = (const float*)d_in[2];
    const float* W1    = (const float*)d_in[3];
    const float* b1    = (const float*)d_in[4];
    const float* Wq1 = (const float*)d_in[5];  const float* bq1 = (const float*)d_in[6];
    const float* Wk1 = (const float*)d_in[7];  const float* bk1 = (const float*)d_in[8];
    const float* Wv1 = (const float*)d_in[9];  const float* bv1 = (const float*)d_in[10];
    const float* We1 = (const float*)d_in[11];
    const float* Ws1 = (const float*)d_in[12]; const float* bs1 = (const float*)d_in[13];
    const float* Wq2 = (const float*)d_in[14]; const float* bq2 = (const float*)d_in[15];
    const float* Wk2 = (const float*)d_in[16]; const float* bk2 = (const float*)d_in[17];
    const float* Wv2 = (const float*)d_in[18]; const float* bv2 = (const float*)d_in[19];
    const float* We2 = (const float*)d_in[20];
    const float* Ws2 = (const float*)d_in[21]; const float* bs2 = (const float*)d_in[22];

    int N = in_sizes[0] / FIN;
    int E = in_sizes[2] / EDIM;
    const int* src = eidx;
    const int* dst = eidx + E;
    float* out = (float*)d_out;

    // layer 0
    k_l0<<<(N + 255) / 256, 256>>>(x, W1, b1, N);

    // CSR by dst (shared by both layers), with src/edge_attr permutation
    k_zero<<<(N + 255) / 256, 256>>>(N);
    k_hist<<<(E + 255) / 256, 256>>>(dst, E);
    k_scan<<<1, 1024>>>(N, E);
    k_scatter<<<(E + 255) / 256, 256>>>(src, dst, (const float4*)eattr, E);

    // layer 1
    k_proj<F0, 8><<<(N + 7) / 8, D>>>(0, Wq1, bq1, Wk1, bk1, Wv1, bv1, Ws1, bs1, N);
    k_attn<<<(N * 32 + 255) / 256, 256>>>(We1, 0, out, N);

    // layer 2
    k_proj<D, 8><<<(N + 7) / 8, D>>>(1, Wq2, bq2, Wk2, bk2, Wv2, bv2, Ws2, bs2, N);
    k_attn<<<(N * 32 + 255) / 256, 256>>>(We2, 1, out, N);
}